// round 8
// baseline (speedup 1.0000x reference)
#include <cuda_runtime.h>
#include <cuda_bf16.h>
#include <cstdint>
#include <cstddef>

// Problem constants
#define B_  4
#define T_  4096
#define D_  1024
#define H_  16
#define HD_ 64
#define BT_ (B_ * T_)          // 16384 rows
#define BH_ (B_ * H_)          // 64 (b,h) pairs
#define KCH 16                 // T-chunks for kv reduction

// ---------------------------------------------------------------------------
// Scratch (device globals; attn aliases g_k which is dead after kv pooling)
// ---------------------------------------------------------------------------
__device__ float g_q[(size_t)BT_ * D_];
__device__ float g_k[(size_t)BT_ * D_];
__device__ float g_v[(size_t)BT_ * D_];
__device__ float g_kvp[(size_t)KCH * BH_ * HD_ * HD_];
__device__ float g_ksump[(size_t)KCH * BH_ * HD_];
__device__ float g_kv[(size_t)BH_ * HD_ * HD_];
__device__ float g_ksum[(size_t)BH_ * HD_];

__device__ __forceinline__ float phi_fn(float x) {
    return x > 0.f ? x + 1.f : __expf(x);
}

__device__ __forceinline__ uint32_t f2tf32(float x) {
    uint32_t r;
    asm("cvt.rna.tf32.f32 %0, %1;" : "=r"(r) : "f"(x));
    return r;
}

__device__ __forceinline__ void mma_tf32(float* c, const uint32_t* a, const uint32_t* b) {
    asm volatile(
        "mma.sync.aligned.m16n8k8.row.col.f32.tf32.tf32.f32 "
        "{%0,%1,%2,%3}, {%4,%5,%6,%7}, {%8,%9}, {%0,%1,%2,%3};\n"
        : "+f"(c[0]), "+f"(c[1]), "+f"(c[2]), "+f"(c[3])
        : "r"(a[0]), "r"(a[1]), "r"(a[2]), "r"(a[3]), "r"(b[0]), "r"(b[1]));
}

// ---------------------------------------------------------------------------
// tf32 tensor-core GEMM: C[row,col] = sum_k A[row,k] * W[col,k]
// A: M x K row-major, W: N x K row-major. M=16384, N=K=1024.
// Block tile 256x128, BK=8, double-buffered. 8 warps (4x2), warp tile 64x64.
// Conflict-free smem strides (264 / 136 words; bank = tig*8+gid permutation).
// mode bit0 = phi epilogue, bit1 = zero masked rows (mask int32, AFTER phi).
// ---------------------------------------------------------------------------
__global__ __launch_bounds__(256) void gemm_tf32(
    const float* __restrict__ A,
    const float* __restrict__ W,
    float* __restrict__ C,
    const int* __restrict__ mask,
    int mode)
{
    const int K = D_;
    const int N = D_;
    __shared__ uint32_t As[2][8][264];   // 256 rows + pad
    __shared__ uint32_t Bs[2][8][136];   // 128 rows + pad

    const int tid  = threadIdx.x;
    const int wid  = tid >> 5;
    const int lane = tid & 31;
    const int gid  = lane >> 2;   // 0..7
    const int tig  = lane & 3;    // 0..3
    const int warpM = wid >> 1;   // 0..3 -> 64 rows each
    const int warpN = wid & 1;    // 0..1 -> 64 cols each

    const int rowBase = blockIdx.x * 256;
    const int colBase = blockIdx.y * 128;

    const int lrowB = tid >> 1;           // 0..127
    const int lkB   = (tid & 1) * 4;      // 0 or 4

    float acc[4][8][4];
    #pragma unroll
    for (int mt = 0; mt < 4; mt++)
        #pragma unroll
        for (int nt = 0; nt < 8; nt++)
            #pragma unroll
            for (int i = 0; i < 4; i++)
                acc[mt][nt][i] = 0.f;

    const float* Ap = A + (size_t)(rowBase + tid) * K;        // 8 floats/thread
    const float* Wp = W + (size_t)(colBase + lrowB) * K + lkB; // 4 floats/thread

    float ag[8], bg[4];
    {
        float4 a0 = *(const float4*)(Ap + 0);
        float4 a1 = *(const float4*)(Ap + 4);
        float4 b0 = *(const float4*)(Wp + 0);
        ag[0]=a0.x; ag[1]=a0.y; ag[2]=a0.z; ag[3]=a0.w;
        ag[4]=a1.x; ag[5]=a1.y; ag[6]=a1.z; ag[7]=a1.w;
        bg[0]=b0.x; bg[1]=b0.y; bg[2]=b0.z; bg[3]=b0.w;
        #pragma unroll
        for (int j = 0; j < 8; j++) As[0][j][tid] = f2tf32(ag[j]);
        #pragma unroll
        for (int j = 0; j < 4; j++) Bs[0][lkB + j][lrowB] = f2tf32(bg[j]);
    }
    __syncthreads();

    int buf = 0;
    for (int kb = 8; kb < K + 8; kb += 8) {
        const bool has_next = (kb < K);
        if (has_next) {
            float4 a0 = *(const float4*)(Ap + kb + 0);
            float4 a1 = *(const float4*)(Ap + kb + 4);
            float4 b0 = *(const float4*)(Wp + kb);
            ag[0]=a0.x; ag[1]=a0.y; ag[2]=a0.z; ag[3]=a0.w;
            ag[4]=a1.x; ag[5]=a1.y; ag[6]=a1.z; ag[7]=a1.w;
            bg[0]=b0.x; bg[1]=b0.y; bg[2]=b0.z; bg[3]=b0.w;
        }

        // compute on current buffer: one K=8 step, 32 MMAs
        {
            uint32_t af[4][4];
            #pragma unroll
            for (int mt = 0; mt < 4; mt++) {
                const int m0 = warpM * 64 + mt * 16;
                af[mt][0] = As[buf][tig    ][m0 + gid    ];
                af[mt][1] = As[buf][tig    ][m0 + gid + 8];
                af[mt][2] = As[buf][tig + 4][m0 + gid    ];
                af[mt][3] = As[buf][tig + 4][m0 + gid + 8];
            }
            uint32_t bf[8][2];
            #pragma unroll
            for (int nt = 0; nt < 8; nt++) {
                const int n0 = warpN * 64 + nt * 8;
                bf[nt][0] = Bs[buf][tig    ][n0 + gid];
                bf[nt][1] = Bs[buf][tig + 4][n0 + gid];
            }
            #pragma unroll
            for (int mt = 0; mt < 4; mt++)
                #pragma unroll
                for (int nt = 0; nt < 8; nt++)
                    mma_tf32(acc[mt][nt], af[mt], bf[nt]);
        }

        if (has_next) {
            #pragma unroll
            for (int j = 0; j < 8; j++) As[buf ^ 1][j][tid] = f2tf32(ag[j]);
            #pragma unroll
            for (int j = 0; j < 4; j++) Bs[buf ^ 1][lkB + j][lrowB] = f2tf32(bg[j]);
        }
        __syncthreads();
        buf ^= 1;
    }

    // Epilogue
    const bool do_phi  = (mode & 1) != 0;
    const bool do_mask = (mode & 2) != 0;

    #pragma unroll
    for (int mt = 0; mt < 4; mt++) {
        const int r0 = rowBase + warpM * 64 + mt * 16 + gid;
        const int r1 = r0 + 8;
        bool mz0 = false, mz1 = false;
        if (do_mask) { mz0 = (mask[r0] != 0); mz1 = (mask[r1] != 0); }
        #pragma unroll
        for (int nt = 0; nt < 8; nt++) {
            const int c = colBase + warpN * 64 + nt * 8 + 2 * tig;
            float v00 = acc[mt][nt][0], v01 = acc[mt][nt][1];
            float v10 = acc[mt][nt][2], v11 = acc[mt][nt][3];
            if (do_phi) { v00 = phi_fn(v00); v01 = phi_fn(v01);
                          v10 = phi_fn(v10); v11 = phi_fn(v11); }
            if (do_mask) {
                if (mz0) { v00 = 0.f; v01 = 0.f; }
                if (mz1) { v10 = 0.f; v11 = 0.f; }
            }
            *(float2*)(C + (size_t)r0 * N + c) = make_float2(v00, v01);
            *(float2*)(C + (size_t)r1 * N + c) = make_float2(v10, v11);
        }
    }
}

// ---------------------------------------------------------------------------
// kv pooling, T split into KCH chunks. grid (BH, 4, KCH), 256 t per chunk.
// ---------------------------------------------------------------------------
__global__ __launch_bounds__(256) void kv_reduce_part(
    const float* __restrict__ k,
    const float* __restrict__ v,
    float* __restrict__ kvp,
    float* __restrict__ ksump)
{
    const int bh = blockIdx.x;
    const int jt = blockIdx.y;
    const int ch = blockIdx.z;
    const int b  = bh >> 4;
    const int h  = bh & 15;
    const int jbase = jt * 16;
    const int tstart = ch * (T_ / KCH);

    __shared__ float ks[64][64];
    __shared__ float vs[64][16];

    const int tid = threadIdx.x;
    const int i   = tid & 63;
    const int jj0 = (tid >> 6) * 4;

    float acc0 = 0.f, acc1 = 0.f, acc2 = 0.f, acc3 = 0.f, ksacc = 0.f;
    const size_t base = ((size_t)b * T_) * D_ + h * HD_;

    for (int t0 = tstart; t0 < tstart + T_ / KCH; t0 += 64) {
        #pragma unroll
        for (int r = 0; r < 16; r++) {
            int idx = r * 256 + tid;
            int tl = idx >> 6, ii = idx & 63;
            ks[tl][ii] = k[base + (size_t)(t0 + tl) * D_ + ii];
        }
        #pragma unroll
        for (int r = 0; r < 4; r++) {
            int idx = r * 256 + tid;
            int tl = idx >> 4, jj = idx & 15;
            vs[tl][jj] = v[base + (size_t)(t0 + tl) * D_ + jbase + jj];
        }
        __syncthreads();

        #pragma unroll 8
        for (int tl = 0; tl < 64; tl++) {
            float kk = ks[tl][i];
            ksacc += kk;
            acc0 = fmaf(kk, vs[tl][jj0 + 0], acc0);
            acc1 = fmaf(kk, vs[tl][jj0 + 1], acc1);
            acc2 = fmaf(kk, vs[tl][jj0 + 2], acc2);
            acc3 = fmaf(kk, vs[tl][jj0 + 3], acc3);
        }
        __syncthreads();
    }

    float* kvb = kvp + ((size_t)ch * BH_ + bh) * HD_ * HD_;
    kvb[i * HD_ + jbase + jj0 + 0] = acc0;
    kvb[i * HD_ + jbase + jj0 + 1] = acc1;
    kvb[i * HD_ + jbase + jj0 + 2] = acc2;
    kvb[i * HD_ + jbase + jj0 + 3] = acc3;
    if (jt == 0 && tid < 64)
        ksump[((size_t)ch * BH_ + bh) * HD_ + tid] = ksacc;
}

__global__ void kv_finalize(const float* __restrict__ kvp, float* __restrict__ kv)
{
    const int idx = blockIdx.x * 256 + threadIdx.x;
    float s = 0.f;
    #pragma unroll
    for (int c = 0; c < KCH; c++)
        s += kvp[(size_t)c * (BH_ * HD_ * HD_) + idx];
    kv[idx] = s;
}

__global__ void ksum_finalize(const float* __restrict__ ksump, float* __restrict__ ksum)
{
    const int idx = blockIdx.x * 256 + threadIdx.x;
    float s = 0.f;
    #pragma unroll
    for (int c = 0; c < KCH; c++)
        s += ksump[(size_t)c * (BH_ * HD_) + idx];
    ksum[idx] = s;
}

// ---------------------------------------------------------------------------
// apply: warp-per-row, no intra-loop block syncs.
// ---------------------------------------------------------------------------
__global__ __launch_bounds__(256) void attn_apply(
    const float* __restrict__ q,
    const float* __restrict__ kv,
    const float* __restrict__ ksum,
    float* __restrict__ attn)
{
    const int bh = blockIdx.x;
    const int b  = bh >> 4;
    const int h  = bh & 15;

    __shared__ float kvs[64][66];
    __shared__ float kss[64];

    const int tid = threadIdx.x;
    const float* kvb = kv + (size_t)bh * HD_ * HD_;
    #pragma unroll
    for (int r = 0; r < 16; r++) {
        int idx = r * 256 + tid;
        kvs[idx >> 6][idx & 63] = kvb[idx];
    }
    if (tid < 64) kss[tid] = ksum[bh * HD_ + tid];
    __syncthreads();

    const int wid  = tid >> 5;
    const int lane = tid & 31;
    const size_t base = ((size_t)b * T_) * D_ + h * HD_;

    for (int it = 0; it < 32; it++) {
        const int t = blockIdx.y * 256 + wid * 32 + it;
        const float* qr = q + base + (size_t)t * D_;
        const float2 qv = *(const float2*)(qr + 2 * lane);

        float o0 = 0.f, o1 = 0.f, nrm = 0.f;
        #pragma unroll
        for (int d = 0; d < 64; d++) {
            const float src = (d & 1) ? qv.y : qv.x;
            const float qd = __shfl_sync(0xffffffffu, src, d >> 1);
            o0  = fmaf(qd, kvs[d][2 * lane    ], o0);
            o1  = fmaf(qd, kvs[d][2 * lane + 1], o1);
            nrm = fmaf(qd, kss[d], nrm);
        }
        const float inv = 1.f / fmaxf(nrm, 1e-6f);
        *(float2*)(attn + base + (size_t)t * D_ + 2 * lane) = make_float2(o0 * inv, o1 * inv);
    }
}

// ---------------------------------------------------------------------------
// Launch
// ---------------------------------------------------------------------------
extern "C" void kernel_launch(void* const* d_in, const int* in_sizes, int n_in,
                              void* d_out, int out_size)
{
    (void)in_sizes; (void)n_in; (void)out_size;
    const float* x    = (const float*)d_in[0];
    const int*   mask = (const int*)d_in[1];     // bool marshaled as int32
    const float* Wq   = (const float*)d_in[2];
    const float* Wk   = (const float*)d_in[3];
    const float* Wv   = (const float*)d_in[4];
    const float* Wo   = (const float*)d_in[5];
    float* out = (float*)d_out;

    float *q, *k, *v, *kvp, *ksump, *kv, *ksum;
    cudaGetSymbolAddress((void**)&q,     g_q);
    cudaGetSymbolAddress((void**)&k,     g_k);
    cudaGetSymbolAddress((void**)&v,     g_v);
    cudaGetSymbolAddress((void**)&kvp,   g_kvp);
    cudaGetSymbolAddress((void**)&ksump, g_ksump);
    cudaGetSymbolAddress((void**)&kv,    g_kv);
    cudaGetSymbolAddress((void**)&ksum,  g_ksum);
    float* attn = k;   // alias: k dead after kv pooling

    dim3 gemm_grid(BT_ / 256, D_ / 128);   // 64 x 8 = 512 blocks

    gemm_tf32<<<gemm_grid, 256>>>(x, Wq, q, nullptr, 1);
    gemm_tf32<<<gemm_grid, 256>>>(x, Wk, k, mask,   3);
    gemm_tf32<<<gemm_grid, 256>>>(x, Wv, v, mask,   2);

    kv_reduce_part<<<dim3(BH_, 4, KCH), 256>>>(k, v, kvp, ksump);
    kv_finalize<<<(BH_ * HD_ * HD_) / 256, 256>>>(kvp, kv);
    ksum_finalize<<<(BH_ * HD_) / 256, 256>>>(ksump, ksum);

    attn_apply<<<dim3(BH_, T_ / 256), 256>>>(q, kv, ksum, attn);

    gemm_tf32<<<gemm_grid, 256>>>(attn, Wo, out, nullptr, 0);
}